// round 13
// baseline (speedup 1.0000x reference)
#include <cuda_runtime.h>
#include <cuda_fp16.h>
#include <math.h>
#include <stdint.h>

// Problem shape (fixed)
#define BBATCH 8
#define QQ 1024
#define KK 4096
#define HH 512
#define OUT_ELEMS (BBATCH * QQ * HH)

// Pre-split fp16 operands (hi/lo) in gmem
__device__ __half g_outp_hi[(size_t)BBATCH * QQ * HH];
__device__ __half g_outp_lo[(size_t)BBATCH * QQ * HH];
__device__ __half g_ctx_hi [(size_t)BBATCH * KK * HH];   // [b][k][h]
__device__ __half g_ctx_lo [(size_t)BBATCH * KK * HH];
__device__ __half g_ctxT_hi[(size_t)BBATCH * HH * KK];   // [b][h][k]
__device__ __half g_ctxT_lo[(size_t)BBATCH * HH * KK];
__device__ __half g_attn_hi[(size_t)BBATCH * QQ * KK];
__device__ __half g_attn_lo[(size_t)BBATCH * QQ * KK];
__device__ __half g_mix_hi [(size_t)BBATCH * QQ * HH];
__device__ __half g_mix_lo [(size_t)BBATCH * QQ * HH];
__device__ __half g_W_hi   [(size_t)HH * 2 * HH];
__device__ __half g_W_lo   [(size_t)HH * 2 * HH];

// ---------------------------------------------------------------------------
// helpers
// ---------------------------------------------------------------------------
__device__ __forceinline__ uint32_t smem_u32(const void* p) {
    uint32_t a;
    asm("{ .reg .u64 t; cvta.to.shared.u64 t, %1; cvt.u32.u64 %0, t; }" : "=r"(a) : "l"(p));
    return a;
}
__device__ __forceinline__ void ldsm4(uint32_t* r, uint32_t addr) {
    asm volatile("ldmatrix.sync.aligned.m8n8.x4.shared.b16 {%0,%1,%2,%3}, [%4];"
                 : "=r"(r[0]), "=r"(r[1]), "=r"(r[2]), "=r"(r[3]) : "r"(addr));
}
// fp16 operands, fp32 accumulate (hh term)
__device__ __forceinline__ void mma_f32(float* c, const uint32_t* a, const uint32_t* b) {
    asm volatile(
        "mma.sync.aligned.m16n8k16.row.col.f32.f16.f16.f32 "
        "{%0,%1,%2,%3}, {%4,%5,%6,%7}, {%8,%9}, {%0,%1,%2,%3};"
        : "+f"(c[0]), "+f"(c[1]), "+f"(c[2]), "+f"(c[3])
        : "r"(a[0]), "r"(a[1]), "r"(a[2]), "r"(a[3]), "r"(b[0]), "r"(b[1]));
}
// fp16 operands, fp16 accumulate (cross terms, 2x rate)
__device__ __forceinline__ void mma_f16(uint32_t* c, const uint32_t* a, const uint32_t* b) {
    asm volatile(
        "mma.sync.aligned.m16n8k16.row.col.f16.f16.f16.f16 "
        "{%0,%1}, {%2,%3,%4,%5}, {%6,%7}, {%0,%1};"
        : "+r"(c[0]), "+r"(c[1])
        : "r"(a[0]), "r"(a[1]), "r"(a[2]), "r"(a[3]), "r"(b[0]), "r"(b[1]));
}
__device__ __forceinline__ void cp16(uint32_t dst, const void* src) {
    asm volatile("cp.async.cg.shared.global [%0], [%1], 16;" :: "r"(dst), "l"(src));
}
#define CP_COMMIT() asm volatile("cp.async.commit_group;" ::: "memory")
#define CP_WAIT0()  asm volatile("cp.async.wait_group 0;" ::: "memory")

// fp32 float4 -> hi/lo fp16 packed
__device__ __forceinline__ void split4h(float4 v, uint2& ph, uint2& pl) {
    __half h0 = __float2half_rn(v.x);
    __half h1 = __float2half_rn(v.y);
    __half h2 = __float2half_rn(v.z);
    __half h3 = __float2half_rn(v.w);
    __half l0 = __float2half_rn(v.x - __half2float(h0));
    __half l1 = __float2half_rn(v.y - __half2float(h1));
    __half l2 = __float2half_rn(v.z - __half2float(h2));
    __half l3 = __float2half_rn(v.w - __half2float(h3));
    ph.x = (uint32_t)__half_as_ushort(h0) | ((uint32_t)__half_as_ushort(h1) << 16);
    ph.y = (uint32_t)__half_as_ushort(h2) | ((uint32_t)__half_as_ushort(h3) << 16);
    pl.x = (uint32_t)__half_as_ushort(l0) | ((uint32_t)__half_as_ushort(l1) << 16);
    pl.y = (uint32_t)__half_as_ushort(l2) | ((uint32_t)__half_as_ushort(l3) << 16);
}

// SMEM: rows of 80 bytes (64B data + 16B pad). Arrays: Ah, Al, Bh, Bl.
#define ROWB   80
#define ARR_B  (128 * ROWB)          // 10240 B
#define STAGE_B (4 * ARR_B)          // 40960 B
#define SMEM_TOTAL (2 * STAGE_B)     // 81920 B

// ---------------------------------------------------------------------------
// fp16 hi/lo NT GEMM: C[m][n] = sum_k A[m][k]*B[n][k]
// hh term f32-accum; hl+lh cross terms f16-accum.
// MODE 0: scores (+mask)  1: mix (emit hi/lo)  2: out (+bias, tanh)
// CTA 128x128, 8 warps (4Mx2N, warp 32x64), K chunk 32, cp.async 2-stage.
// ---------------------------------------------------------------------------
template <int MODE>
__global__ __launch_bounds__(256, 2) void gemm_kernel(
    const __half* __restrict__ A1h, const __half* __restrict__ A1l,
    const __half* __restrict__ A2h, const __half* __restrict__ A2l,
    const __half* __restrict__ Bhg, const __half* __restrict__ Blg,
    const int* __restrict__ mask, const float* __restrict__ bias,
    float* __restrict__ attn, __half* __restrict__ mixh,
    __half* __restrict__ mixl, float* __restrict__ outpart)
{
    extern __shared__ __align__(16) char smem[];
    const uint32_t sbase = smem_u32(smem);

    const int t = threadIdx.x, wid = t >> 5, lid = t & 31;
    const int wx = wid & 1;       // N: 2 x 64
    const int wy = wid >> 1;      // M: 4 x 32
    const int b = blockIdx.z, q0 = blockIdx.y * 128, n0 = blockIdx.x * 128;
    const int KLEN = (MODE == 0) ? HH : (MODE == 1) ? KK : 2 * HH;
    const int NCH = KLEN / 32;
    const int lda = (MODE == 1) ? KK : HH;
    const int ldb = (MODE == 0) ? HH : (MODE == 1) ? KK : 2 * HH;

    float    acc [2][8][4];     // f32 accum (hh)      64 regs
    uint32_t cacc[2][8][2];     // f16 accum (hl+lh)   32 regs
    #pragma unroll
    for (int mt = 0; mt < 2; mt++)
        #pragma unroll
        for (int nt = 0; nt < 8; nt++) {
            #pragma unroll
            for (int j = 0; j < 4; j++) acc[mt][nt][j] = 0.f;
            cacc[mt][nt][0] = 0u; cacc[mt][nt][1] = 0u;
        }

    // cp.async coords: 256 threads, 2 iters, 4 arrays
    const int lrow[2] = { (t + 0) >> 2, (t + 256) >> 2 };
    const int lcu     = (t & 3) << 3;       // element offset (8 fp16 = 16B)

    auto issue_chunk = [&](int ch, int st) {
        const int k0 = ch * 32;
        const __half *ah, *al;
        int ak0;
        if (MODE == 2 && k0 >= HH) { ah = A2h; al = A2l; ak0 = k0 - HH; }
        else                       { ah = A1h; al = A1l; ak0 = k0; }
        const __half* arow_h = ah + ((size_t)(b * QQ + q0)) * lda + ak0;
        const __half* arow_l = al + ((size_t)(b * QQ + q0)) * lda + ak0;
        const size_t bbase = (MODE == 2) ? ((size_t)n0 * ldb + k0)
                                         : (((size_t)(b * (MODE == 0 ? KK : HH) + n0)) * ldb + k0);
        const __half* brow_h = Bhg + bbase;
        const __half* brow_l = Blg + bbase;
        const uint32_t sb = sbase + st * STAGE_B;
        #pragma unroll
        for (int i = 0; i < 2; i++) {
            const uint32_t doff = (uint32_t)(lrow[i] * ROWB + (lcu << 1));
            cp16(sb + doff,              arow_h + (size_t)lrow[i] * lda + lcu);
            cp16(sb + ARR_B + doff,      arow_l + (size_t)lrow[i] * lda + lcu);
            cp16(sb + 2 * ARR_B + doff,  brow_h + (size_t)lrow[i] * ldb + lcu);
            cp16(sb + 3 * ARR_B + doff,  brow_l + (size_t)lrow[i] * ldb + lcu);
        }
        CP_COMMIT();
    };

    const int lane16 = lid & 15;

    issue_chunk(0, 0);

    for (int ch = 0; ch < NCH; ch++) {
        CP_WAIT0();
        __syncthreads();
        if (ch + 1 < NCH) issue_chunk(ch + 1, (ch + 1) & 1);

        const uint32_t sb  = sbase + (ch & 1) * STAGE_B;
        const uint32_t sAh = sb, sAl = sb + ARR_B, sBh = sb + 2 * ARR_B, sBl = sb + 3 * ARR_B;

        #pragma unroll
        for (int kt = 0; kt < 2; kt++) {
            uint32_t afh[2][4], afl[2][4];
            #pragma unroll
            for (int mt = 0; mt < 2; mt++) {
                uint32_t off = (uint32_t)((wy * 32 + mt * 16 + lane16) * ROWB
                                          + kt * 32 + ((lid >> 4) << 4));
                ldsm4(afh[mt], sAh + off);
                ldsm4(afl[mt], sAl + off);
            }
            #pragma unroll
            for (int np = 0; np < 4; np++) {
                const int nt0 = np * 2, nt1 = np * 2 + 1;
                const int brow = wx * 64 + np * 16 + ((lid & 16) >> 1) + (lid & 7);
                uint32_t boff = (uint32_t)(brow * ROWB + kt * 32 + (((lid >> 3) & 1) << 4));
                uint32_t bh[4], bl[4];
                ldsm4(bh, sBh + boff);
                ldsm4(bl, sBl + boff);
                // hh term: f32 accumulate (4 MMAs)
                #pragma unroll
                for (int mt = 0; mt < 2; mt++) {
                    mma_f32(acc[mt][nt0], afh[mt], bh);
                    mma_f32(acc[mt][nt1], afh[mt], bh + 2);
                }
                // hl term: f16 accumulate
                #pragma unroll
                for (int mt = 0; mt < 2; mt++) {
                    mma_f16(cacc[mt][nt0], afh[mt], bl);
                    mma_f16(cacc[mt][nt1], afh[mt], bl + 2);
                }
                // lh term: f16 accumulate
                #pragma unroll
                for (int mt = 0; mt < 2; mt++) {
                    mma_f16(cacc[mt][nt0], afl[mt], bh);
                    mma_f16(cacc[mt][nt1], afl[mt], bh + 2);
                }
            }
        }
        __syncthreads();
    }

    // ---- epilogue: v = acc + float(cacc) ----
    const int rq = lid >> 2;          // 0..7
    const int cq = (lid & 3) * 2;     // 0,2,4,6
    #pragma unroll
    for (int mt = 0; mt < 2; mt++) {
        #pragma unroll
        for (int nt = 0; nt < 8; nt++) {
            const int col = n0 + wx * 64 + nt * 8 + cq;
            #pragma unroll
            for (int half = 0; half < 2; half++) {
                const int row = q0 + wy * 32 + mt * 16 + rq + half * 8;
                __half2 cp = *(__half2*)&cacc[mt][nt][half];
                float v0 = acc[mt][nt][half * 2 + 0] + __low2float(cp);
                float v1 = acc[mt][nt][half * 2 + 1] + __high2float(cp);
                if (MODE == 0) {
                    const size_t o = ((size_t)(b * QQ + row)) * KK + col;
                    int2 mk = *(const int2*)(mask + o);
                    float2 w2;
                    w2.x = mk.x ? -INFINITY : v0;
                    w2.y = mk.y ? -INFINITY : v1;
                    *(float2*)(attn + o) = w2;
                } else if (MODE == 1) {
                    const size_t o = ((size_t)(b * QQ + row)) * HH + col;
                    __half h0 = __float2half_rn(v0);
                    __half h1 = __float2half_rn(v1);
                    __half l0 = __float2half_rn(v0 - __half2float(h0));
                    __half l1 = __float2half_rn(v1 - __half2float(h1));
                    uint32_t ph = (uint32_t)__half_as_ushort(h0) | ((uint32_t)__half_as_ushort(h1) << 16);
                    uint32_t pl = (uint32_t)__half_as_ushort(l0) | ((uint32_t)__half_as_ushort(l1) << 16);
                    *(uint32_t*)(mixh + o) = ph;
                    *(uint32_t*)(mixl + o) = pl;
                } else {
                    const size_t o = ((size_t)(b * QQ + row)) * HH + col;
                    float2 bi = *(const float2*)(bias + col);
                    *(float2*)(outpart + o) = make_float2(tanhf(v0 + bi.x), tanhf(v1 + bi.y));
                }
            }
        }
    }
}

// ---------------------------------------------------------------------------
// Generic fp32 -> hi/lo fp16 split
// ---------------------------------------------------------------------------
__global__ __launch_bounds__(256) void split_kernel(
    const float* __restrict__ src, __half* __restrict__ hi,
    __half* __restrict__ lo, size_t n4)
{
    size_t i = (size_t)blockIdx.x * 256 + threadIdx.x;
    if (i >= n4) return;
    float4 v = *(const float4*)(src + i * 4);
    uint2 ph, pl;
    split4h(v, ph, pl);
    *(uint2*)(hi + i * 4) = ph;
    *(uint2*)(lo + i * 4) = pl;
}

// ---------------------------------------------------------------------------
// ctx: one read -> ctx_hi/lo [b][k][h] AND ctxT_hi/lo [b][h][k]
// ---------------------------------------------------------------------------
__global__ __launch_bounds__(256) void ctx_prep_kernel(
    const float* __restrict__ ctx,
    __half* __restrict__ ch, __half* __restrict__ cl,
    __half* __restrict__ th, __half* __restrict__ tl)
{
    __shared__ float tile[32][33];
    const int b = blockIdx.z, k0 = blockIdx.x * 32, h0 = blockIdx.y * 32;
    const int t = threadIdx.x;
    const int tx = t & 31, ty = t >> 5;
    const float* src = ctx + ((size_t)(b * KK + k0)) * HH + h0;
    #pragma unroll
    for (int j = ty; j < 32; j += 8) {
        float v = src[(size_t)j * HH + tx];
        tile[j][tx] = v;
        __half hh = __float2half_rn(v);
        __half hl = __float2half_rn(v - __half2float(hh));
        size_t o = ((size_t)(b * KK + k0 + j)) * HH + h0 + tx;
        ch[o] = hh;
        cl[o] = hl;
    }
    __syncthreads();
    const int h  = t >> 3;         // 0..31
    const int p0 = t & 7;          // 0..7
    #pragma unroll
    for (int s = 0; s < 2; s++) {
        const int p = p0 + s * 8;          // 0..15
        float v0 = tile[2 * p + 0][h];
        float v1 = tile[2 * p + 1][h];
        __half h0b = __float2half_rn(v0);
        __half h1b = __float2half_rn(v1);
        __half l0b = __float2half_rn(v0 - __half2float(h0b));
        __half l1b = __float2half_rn(v1 - __half2float(h1b));
        uint32_t ph = (uint32_t)__half_as_ushort(h0b) | ((uint32_t)__half_as_ushort(h1b) << 16);
        uint32_t pl = (uint32_t)__half_as_ushort(l0b) | ((uint32_t)__half_as_ushort(l1b) << 16);
        size_t o = ((size_t)(b * HH + h0 + h)) * KK + k0 + 2 * p;
        *(uint32_t*)(th + o) = ph;
        *(uint32_t*)(tl + o) = pl;
    }
}

// ---------------------------------------------------------------------------
// Softmax: one CTA/row, register resident; emits fp32 attn + hi/lo fp16
// ---------------------------------------------------------------------------
__global__ __launch_bounds__(256) void softmax_kernel(
    float* __restrict__ attn, __half* __restrict__ ah, __half* __restrict__ al)
{
    const size_t row = blockIdx.x;
    float4* p = (float4*)(attn + row * KK);
    const int t = threadIdx.x, wid = t >> 5, lid = t & 31;
    __shared__ float red[8];

    float4 v[4];
    float mx = -INFINITY;
    #pragma unroll
    for (int j = 0; j < 4; j++) {
        v[j] = p[t + j * 256];
        mx = fmaxf(mx, fmaxf(fmaxf(v[j].x, v[j].y), fmaxf(v[j].z, v[j].w)));
    }
    #pragma unroll
    for (int s = 16; s > 0; s >>= 1) mx = fmaxf(mx, __shfl_xor_sync(0xffffffffu, mx, s));
    if (lid == 0) red[wid] = mx;
    __syncthreads();
    float m2 = red[0];
    #pragma unroll
    for (int i = 1; i < 8; i++) m2 = fmaxf(m2, red[i]);
    __syncthreads();

    float sum = 0.f;
    #pragma unroll
    for (int j = 0; j < 4; j++) {
        v[j].x = __expf(v[j].x - m2);
        v[j].y = __expf(v[j].y - m2);
        v[j].z = __expf(v[j].z - m2);
        v[j].w = __expf(v[j].w - m2);
        sum += v[j].x + v[j].y + v[j].z + v[j].w;
    }
    #pragma unroll
    for (int s = 16; s > 0; s >>= 1) sum += __shfl_xor_sync(0xffffffffu, sum, s);
    if (lid == 0) red[wid] = sum;
    __syncthreads();
    float tot = 0.f;
    #pragma unroll
    for (int i = 0; i < 8; i++) tot += red[i];
    const float inv = 1.f / tot;

    __half* hrow = ah + row * KK;
    __half* lrow = al + row * KK;
    #pragma unroll
    for (int j = 0; j < 4; j++) {
        v[j].x *= inv; v[j].y *= inv; v[j].z *= inv; v[j].w *= inv;
        p[t + j * 256] = v[j];
        uint2 ph, pl;
        split4h(v[j], ph, pl);
        *(uint2*)(hrow + (size_t)(t + j * 256) * 4) = ph;
        *(uint2*)(lrow + (size_t)(t + j * 256) * 4) = pl;
    }
}

// ---------------------------------------------------------------------------
extern "C" void kernel_launch(void* const* d_in, const int* in_sizes, int n_in,
                              void* d_out, int out_size)
{
    const float* outp = (const float*)d_in[0];   // [B,Q,H]
    const float* ctx  = (const float*)d_in[1];   // [B,K,H]
    const int*   mask = (const int*)d_in[2];     // [B,Q,K]
    const float* W    = (const float*)d_in[3];   // [H,2H]
    const float* bias = (const float*)d_in[4];   // [H]

    float* out_part  = (float*)d_out;
    float* attn_part = (float*)d_out + OUT_ELEMS;

    __half *oh, *ol, *ch, *cl, *cth, *ctl, *ath, *atl, *mh, *ml, *wh, *wl;
    cudaGetSymbolAddress((void**)&oh,  g_outp_hi);
    cudaGetSymbolAddress((void**)&ol,  g_outp_lo);
    cudaGetSymbolAddress((void**)&ch,  g_ctx_hi);
    cudaGetSymbolAddress((void**)&cl,  g_ctx_lo);
    cudaGetSymbolAddress((void**)&cth, g_ctxT_hi);
    cudaGetSymbolAddress((void**)&ctl, g_ctxT_lo);
    cudaGetSymbolAddress((void**)&ath, g_attn_hi);
    cudaGetSymbolAddress((void**)&atl, g_attn_lo);
    cudaGetSymbolAddress((void**)&mh,  g_mix_hi);
    cudaGetSymbolAddress((void**)&ml,  g_mix_lo);
    cudaGetSymbolAddress((void**)&wh,  g_W_hi);
    cudaGetSymbolAddress((void**)&wl,  g_W_lo);

    cudaFuncSetAttribute(gemm_kernel<0>, cudaFuncAttributeMaxDynamicSharedMemorySize, SMEM_TOTAL);
    cudaFuncSetAttribute(gemm_kernel<1>, cudaFuncAttributeMaxDynamicSharedMemorySize, SMEM_TOTAL);
    cudaFuncSetAttribute(gemm_kernel<2>, cudaFuncAttributeMaxDynamicSharedMemorySize, SMEM_TOTAL);

    // Prep: splits + ctx transpose (single ctx read)
    {
        size_t n4;
        n4 = (size_t)BBATCH * QQ * HH / 4;
        split_kernel<<<(unsigned)((n4 + 255) / 256), 256>>>(outp, oh, ol, n4);
        n4 = (size_t)HH * 2 * HH / 4;
        split_kernel<<<(unsigned)((n4 + 255) / 256), 256>>>(W, wh, wl, n4);
        dim3 grid(KK / 32, HH / 32, BBATCH);
        ctx_prep_kernel<<<grid, 256>>>(ctx, ch, cl, cth, ctl);
    }
    // scores (+mask) -> attn region (fp32 logits)
    {
        dim3 grid(KK / 128, QQ / 128, BBATCH);
        gemm_kernel<0><<<grid, 256, SMEM_TOTAL>>>(oh, ol, nullptr, nullptr, ch, cl,
                                                  mask, bias, attn_part, mh, ml, out_part);
    }
    // softmax (emits fp32 attn + hi/lo fp16)
    softmax_kernel<<<BBATCH * QQ, 256>>>(attn_part, ath, atl);
    // mix = attn @ ctx  (emits mix hi/lo fp16)
    {
        dim3 grid(HH / 128, QQ / 128, BBATCH);
        gemm_kernel<1><<<grid, 256, SMEM_TOTAL>>>(ath, atl, nullptr, nullptr, cth, ctl,
                                                  mask, bias, attn_part, mh, ml, out_part);
    }
    // out = tanh([mix|output] @ W^T + b)
    {
        dim3 grid(HH / 128, QQ / 128, BBATCH);
        gemm_kernel<2><<<grid, 256, SMEM_TOTAL>>>(mh, ml, oh, ol, wh, wl,
                                                  mask, bias, attn_part, mh, ml, out_part);
    }
}

// round 14
// speedup vs baseline: 2.2700x; 2.2700x over previous
#include <cuda_runtime.h>
#include <cuda_fp16.h>
#include <math.h>
#include <stdint.h>

// Problem shape (fixed)
#define BBATCH 8
#define QQ 1024
#define KK 4096
#define HH 512
#define OUT_ELEMS (BBATCH * QQ * HH)

// fp16 operands in gmem
__device__ __half g_outp_hi[(size_t)BBATCH * QQ * HH];
__device__ __half g_outp_lo[(size_t)BBATCH * QQ * HH];
__device__ __half g_ctx_hi [(size_t)BBATCH * KK * HH];   // [b][k][h]
__device__ __half g_ctx_lo [(size_t)BBATCH * KK * HH];
__device__ __half g_ctxT_hi[(size_t)BBATCH * HH * KK];   // [b][h][k]
__device__ __half g_attn_hi[(size_t)BBATCH * QQ * KK];
__device__ __half g_mix_hi [(size_t)BBATCH * QQ * HH];
__device__ __half g_W_hi   [(size_t)HH * 2 * HH];

// ---------------------------------------------------------------------------
// helpers
// ---------------------------------------------------------------------------
__device__ __forceinline__ uint32_t smem_u32(const void* p) {
    uint32_t a;
    asm("{ .reg .u64 t; cvta.to.shared.u64 t, %1; cvt.u32.u64 %0, t; }" : "=r"(a) : "l"(p));
    return a;
}
__device__ __forceinline__ void ldsm4(uint32_t* r, uint32_t addr) {
    asm volatile("ldmatrix.sync.aligned.m8n8.x4.shared.b16 {%0,%1,%2,%3}, [%4];"
                 : "=r"(r[0]), "=r"(r[1]), "=r"(r[2]), "=r"(r[3]) : "r"(addr));
}
__device__ __forceinline__ void mma_f32(float* c, const uint32_t* a, const uint32_t* b) {
    asm volatile(
        "mma.sync.aligned.m16n8k16.row.col.f32.f16.f16.f32 "
        "{%0,%1,%2,%3}, {%4,%5,%6,%7}, {%8,%9}, {%0,%1,%2,%3};"
        : "+f"(c[0]), "+f"(c[1]), "+f"(c[2]), "+f"(c[3])
        : "r"(a[0]), "r"(a[1]), "r"(a[2]), "r"(a[3]), "r"(b[0]), "r"(b[1]));
}
__device__ __forceinline__ void mma_f16(uint32_t* c, const uint32_t* a, const uint32_t* b) {
    asm volatile(
        "mma.sync.aligned.m16n8k16.row.col.f16.f16.f16.f16 "
        "{%0,%1}, {%2,%3,%4,%5}, {%6,%7}, {%0,%1};"
        : "+r"(c[0]), "+r"(c[1])
        : "r"(a[0]), "r"(a[1]), "r"(a[2]), "r"(a[3]), "r"(b[0]), "r"(b[1]));
}
__device__ __forceinline__ void cp16(uint32_t dst, const void* src) {
    asm volatile("cp.async.cg.shared.global [%0], [%1], 16;" :: "r"(dst), "l"(src));
}
#define CP_COMMIT() asm volatile("cp.async.commit_group;" ::: "memory")
#define CP_WAIT0()  asm volatile("cp.async.wait_group 0;" ::: "memory")

// fp32 float4 -> hi/lo fp16 packed
__device__ __forceinline__ void split4h(float4 v, uint2& ph, uint2& pl) {
    __half h0 = __float2half_rn(v.x);
    __half h1 = __float2half_rn(v.y);
    __half h2 = __float2half_rn(v.z);
    __half h3 = __float2half_rn(v.w);
    __half l0 = __float2half_rn(v.x - __half2float(h0));
    __half l1 = __float2half_rn(v.y - __half2float(h1));
    __half l2 = __float2half_rn(v.z - __half2float(h2));
    __half l3 = __float2half_rn(v.w - __half2float(h3));
    ph.x = (uint32_t)__half_as_ushort(h0) | ((uint32_t)__half_as_ushort(h1) << 16);
    ph.y = (uint32_t)__half_as_ushort(h2) | ((uint32_t)__half_as_ushort(h3) << 16);
    pl.x = (uint32_t)__half_as_ushort(l0) | ((uint32_t)__half_as_ushort(l1) << 16);
    pl.y = (uint32_t)__half_as_ushort(l2) | ((uint32_t)__half_as_ushort(l3) << 16);
}
__device__ __forceinline__ uint2 cast4h(float4 v) {
    __half h0 = __float2half_rn(v.x);
    __half h1 = __float2half_rn(v.y);
    __half h2 = __float2half_rn(v.z);
    __half h3 = __float2half_rn(v.w);
    uint2 ph;
    ph.x = (uint32_t)__half_as_ushort(h0) | ((uint32_t)__half_as_ushort(h1) << 16);
    ph.y = (uint32_t)__half_as_ushort(h2) | ((uint32_t)__half_as_ushort(h3) << 16);
    return ph;
}

// SMEM: rows of 80 bytes (64B data + 16B pad).
#define ROWB   80
#define ARR_B  (128 * ROWB)          // 10240 B
// MODE 0: 4 arrays/stage (Ah, Al, Bh, Bl); MODE 1/2: 2 arrays (Ah, Bh)
#define SMEM_MAX (2 * 4 * ARR_B)     // 81920 B

// ---------------------------------------------------------------------------
// NT GEMM: C[m][n] = sum_k A[m][k]*B[n][k]
// MODE 0: scores, 3-term split (hh f32-accum, hl+lh f16-accum), +mask
// MODE 1: mix, single-term fp16 (attn_hi @ ctxT_hi), emits mix_hi fp16
// MODE 2: out, single-term fp16 ([mix|outp]_hi @ W_hi), +bias, tanh
// CTA 128x128, 4 warps (2Mx2N, warp 64x64), K chunk 32, cp.async 2-stage.
// ---------------------------------------------------------------------------
template <int MODE>
__global__ __launch_bounds__(128, 2) void gemm_kernel(
    const __half* __restrict__ A1h, const __half* __restrict__ A1l,
    const __half* __restrict__ A2h,
    const __half* __restrict__ Bhg, const __half* __restrict__ Blg,
    const int* __restrict__ mask, const float* __restrict__ bias,
    float* __restrict__ attn, __half* __restrict__ mixh,
    float* __restrict__ outpart)
{
    extern __shared__ __align__(16) char smem[];
    const uint32_t sbase = smem_u32(smem);
    constexpr bool SPLIT = (MODE == 0);
    constexpr int NARR = SPLIT ? 4 : 2;
    constexpr int STAGE_B = NARR * ARR_B;

    const int t = threadIdx.x, wid = t >> 5, lid = t & 31;
    const int wx = wid & 1;       // N: 2 x 64
    const int wy = wid >> 1;      // M: 2 x 64
    const int b = blockIdx.z, q0 = blockIdx.y * 128, n0 = blockIdx.x * 128;
    const int KLEN = (MODE == 0) ? HH : (MODE == 1) ? KK : 2 * HH;
    const int NCH = KLEN / 32;
    const int lda = (MODE == 1) ? KK : HH;
    const int ldb = (MODE == 0) ? HH : (MODE == 1) ? KK : 2 * HH;

    float    acc [4][8][4];
    uint32_t cacc[4][8][2];
    #pragma unroll
    for (int mt = 0; mt < 4; mt++)
        #pragma unroll
        for (int nt = 0; nt < 8; nt++) {
            #pragma unroll
            for (int j = 0; j < 4; j++) acc[mt][nt][j] = 0.f;
            cacc[mt][nt][0] = 0u; cacc[mt][nt][1] = 0u;
        }

    const int lrow[4] = { (t + 0) >> 2, (t + 128) >> 2, (t + 256) >> 2, (t + 384) >> 2 };
    const int lcu    = (t & 3) << 3;       // element offset (8 fp16 = 16B)

    auto issue_chunk = [&](int ch, int st) {
        const int k0 = ch * 32;
        const __half *ah = A1h, *al = A1l;
        int ak0 = k0;
        if (MODE == 2 && k0 >= HH) { ah = A2h; ak0 = k0 - HH; }
        const __half* arow_h = ah + ((size_t)(b * QQ + q0)) * lda + ak0;
        const size_t bbase = (MODE == 2) ? ((size_t)n0 * ldb + k0)
                                         : (((size_t)(b * (MODE == 0 ? KK : HH) + n0)) * ldb + k0);
        const __half* brow_h = Bhg + bbase;
        const uint32_t sb = sbase + st * STAGE_B;
        if (SPLIT) {
            const __half* arow_l = al + ((size_t)(b * QQ + q0)) * lda + ak0;
            const __half* brow_l = Blg + bbase;
            #pragma unroll
            for (int i = 0; i < 4; i++) {
                const uint32_t doff = (uint32_t)(lrow[i] * ROWB + (lcu << 1));
                cp16(sb + doff,              arow_h + (size_t)lrow[i] * lda + lcu);
                cp16(sb + ARR_B + doff,      arow_l + (size_t)lrow[i] * lda + lcu);
                cp16(sb + 2 * ARR_B + doff,  brow_h + (size_t)lrow[i] * ldb + lcu);
                cp16(sb + 3 * ARR_B + doff,  brow_l + (size_t)lrow[i] * ldb + lcu);
            }
        } else {
            #pragma unroll
            for (int i = 0; i < 4; i++) {
                const uint32_t doff = (uint32_t)(lrow[i] * ROWB + (lcu << 1));
                cp16(sb + doff,          arow_h + (size_t)lrow[i] * lda + lcu);
                cp16(sb + ARR_B + doff,  brow_h + (size_t)lrow[i] * ldb + lcu);
            }
        }
        CP_COMMIT();
    };

    const int lane16 = lid & 15;

    issue_chunk(0, 0);

    for (int ch = 0; ch < NCH; ch++) {
        CP_WAIT0();
        __syncthreads();
        if (ch + 1 < NCH) issue_chunk(ch + 1, (ch + 1) & 1);

        const uint32_t sb  = sbase + (ch & 1) * STAGE_B;
        const uint32_t sAh = sb;
        const uint32_t sAl = sb + ARR_B;                       // SPLIT only
        const uint32_t sBh = sb + (SPLIT ? 2 : 1) * ARR_B;
        const uint32_t sBl = sb + 3 * ARR_B;                   // SPLIT only

        #pragma unroll
        for (int kt = 0; kt < 2; kt++) {
            uint32_t afh[4][4], afl[4][4];
            #pragma unroll
            for (int mt = 0; mt < 4; mt++) {
                uint32_t off = (uint32_t)((wy * 64 + mt * 16 + lane16) * ROWB
                                          + kt * 32 + ((lid >> 4) << 4));
                ldsm4(afh[mt], sAh + off);
                if (SPLIT) ldsm4(afl[mt], sAl + off);
            }
            #pragma unroll
            for (int np = 0; np < 4; np++) {
                const int nt0 = np * 2, nt1 = np * 2 + 1;
                const int brow = wx * 64 + np * 16 + ((lid & 16) >> 1) + (lid & 7);
                uint32_t boff = (uint32_t)(brow * ROWB + kt * 32 + (((lid >> 3) & 1) << 4));
                uint32_t bh[4], bl[4];
                ldsm4(bh, sBh + boff);
                if (SPLIT) ldsm4(bl, sBl + boff);
                #pragma unroll
                for (int mt = 0; mt < 4; mt++) {
                    mma_f32(acc[mt][nt0], afh[mt], bh);
                    mma_f32(acc[mt][nt1], afh[mt], bh + 2);
                }
                if (SPLIT) {
                    #pragma unroll
                    for (int mt = 0; mt < 4; mt++) {
                        mma_f16(cacc[mt][nt0], afh[mt], bl);
                        mma_f16(cacc[mt][nt1], afh[mt], bl + 2);
                    }
                    #pragma unroll
                    for (int mt = 0; mt < 4; mt++) {
                        mma_f16(cacc[mt][nt0], afl[mt], bh);
                        mma_f16(cacc[mt][nt1], afl[mt], bh + 2);
                    }
                }
            }
        }
        __syncthreads();
    }

    // ---- epilogue ----
    const int rq = lid >> 2;          // 0..7
    const int cq = (lid & 3) * 2;     // 0,2,4,6
    #pragma unroll
    for (int mt = 0; mt < 4; mt++) {
        #pragma unroll
        for (int nt = 0; nt < 8; nt++) {
            const int col = n0 + wx * 64 + nt * 8 + cq;
            #pragma unroll
            for (int half = 0; half < 2; half++) {
                const int row = q0 + wy * 64 + mt * 16 + rq + half * 8;
                float v0 = acc[mt][nt][half * 2 + 0];
                float v1 = acc[mt][nt][half * 2 + 1];
                if (MODE == 0) {
                    __half2 cp = *(__half2*)&cacc[mt][nt][half];
                    v0 += __low2float(cp);
                    v1 += __high2float(cp);
                    const size_t o = ((size_t)(b * QQ + row)) * KK + col;
                    int2 mk = *(const int2*)(mask + o);
                    float2 w2;
                    w2.x = mk.x ? -INFINITY : v0;
                    w2.y = mk.y ? -INFINITY : v1;
                    *(float2*)(attn + o) = w2;
                } else if (MODE == 1) {
                    const size_t o = ((size_t)(b * QQ + row)) * HH + col;
                    __half h0 = __float2half_rn(v0);
                    __half h1 = __float2half_rn(v1);
                    uint32_t ph = (uint32_t)__half_as_ushort(h0) | ((uint32_t)__half_as_ushort(h1) << 16);
                    *(uint32_t*)(mixh + o) = ph;
                } else {
                    const size_t o = ((size_t)(b * QQ + row)) * HH + col;
                    float2 bi = *(const float2*)(bias + col);
                    *(float2*)(outpart + o) = make_float2(tanhf(v0 + bi.x), tanhf(v1 + bi.y));
                }
            }
        }
    }
}

// ---------------------------------------------------------------------------
// fp32 -> hi/lo fp16 split
// ---------------------------------------------------------------------------
__global__ __launch_bounds__(256) void split_kernel(
    const float* __restrict__ src, __half* __restrict__ hi,
    __half* __restrict__ lo, size_t n4)
{
    size_t i = (size_t)blockIdx.x * 256 + threadIdx.x;
    if (i >= n4) return;
    float4 v = *(const float4*)(src + i * 4);
    uint2 ph, pl;
    split4h(v, ph, pl);
    *(uint2*)(hi + i * 4) = ph;
    *(uint2*)(lo + i * 4) = pl;
}

// fp32 -> fp16 cast only
__global__ __launch_bounds__(256) void cast_kernel(
    const float* __restrict__ src, __half* __restrict__ hi, size_t n4)
{
    size_t i = (size_t)blockIdx.x * 256 + threadIdx.x;
    if (i >= n4) return;
    float4 v = *(const float4*)(src + i * 4);
    *(uint2*)(hi + i * 4) = cast4h(v);
}

// ---------------------------------------------------------------------------
// ctx: one read -> ctx_hi/lo [b][k][h] AND ctxT_hi [b][h][k]
// ---------------------------------------------------------------------------
__global__ __launch_bounds__(256) void ctx_prep_kernel(
    const float* __restrict__ ctx,
    __half* __restrict__ ch, __half* __restrict__ cl,
    __half* __restrict__ th)
{
    __shared__ float tile[32][33];
    const int b = blockIdx.z, k0 = blockIdx.x * 32, h0 = blockIdx.y * 32;
    const int t = threadIdx.x;
    const int tx = t & 31, ty = t >> 5;
    const float* src = ctx + ((size_t)(b * KK + k0)) * HH + h0;
    #pragma unroll
    for (int j = ty; j < 32; j += 8) {
        float v = src[(size_t)j * HH + tx];
        tile[j][tx] = v;
        __half hh = __float2half_rn(v);
        __half hl = __float2half_rn(v - __half2float(hh));
        size_t o = ((size_t)(b * KK + k0 + j)) * HH + h0 + tx;
        ch[o] = hh;
        cl[o] = hl;
    }
    __syncthreads();
    const int h  = t >> 3;         // 0..31
    const int p0 = t & 7;          // 0..7
    #pragma unroll
    for (int s = 0; s < 2; s++) {
        const int p = p0 + s * 8;          // 0..15
        float v0 = tile[2 * p + 0][h];
        float v1 = tile[2 * p + 1][h];
        __half h0b = __float2half_rn(v0);
        __half h1b = __float2half_rn(v1);
        uint32_t ph = (uint32_t)__half_as_ushort(h0b) | ((uint32_t)__half_as_ushort(h1b) << 16);
        size_t o = ((size_t)(b * HH + h0 + h)) * KK + k0 + 2 * p;
        *(uint32_t*)(th + o) = ph;
    }
}

// ---------------------------------------------------------------------------
// Softmax: one CTA/row, register resident; emits fp32 attn + fp16 hi
// ---------------------------------------------------------------------------
__global__ __launch_bounds__(256) void softmax_kernel(
    float* __restrict__ attn, __half* __restrict__ ah)
{
    const size_t row = blockIdx.x;
    float4* p = (float4*)(attn + row * KK);
    const int t = threadIdx.x, wid = t >> 5, lid = t & 31;
    __shared__ float red[8];

    float4 v[4];
    float mx = -INFINITY;
    #pragma unroll
    for (int j = 0; j < 4; j++) {
        v[j] = p[t + j * 256];
        mx = fmaxf(mx, fmaxf(fmaxf(v[j].x, v[j].y), fmaxf(v[j].z, v[j].w)));
    }
    #pragma unroll
    for (int s = 16; s > 0; s >>= 1) mx = fmaxf(mx, __shfl_xor_sync(0xffffffffu, mx, s));
    if (lid == 0) red[wid] = mx;
    __syncthreads();
    float m2 = red[0];
    #pragma unroll
    for (int i = 1; i < 8; i++) m2 = fmaxf(m2, red[i]);
    __syncthreads();

    float sum = 0.f;
    #pragma unroll
    for (int j = 0; j < 4; j++) {
        v[j].x = __expf(v[j].x - m2);
        v[j].y = __expf(v[j].y - m2);
        v[j].z = __expf(v[j].z - m2);
        v[j].w = __expf(v[j].w - m2);
        sum += v[j].x + v[j].y + v[j].z + v[j].w;
    }
    #pragma unroll
    for (int s = 16; s > 0; s >>= 1) sum += __shfl_xor_sync(0xffffffffu, sum, s);
    if (lid == 0) red[wid] = sum;
    __syncthreads();
    float tot = 0.f;
    #pragma unroll
    for (int i = 0; i < 8; i++) tot += red[i];
    const float inv = 1.f / tot;

    __half* hrow = ah + row * KK;
    #pragma unroll
    for (int j = 0; j < 4; j++) {
        v[j].x *= inv; v[j].y *= inv; v[j].z *= inv; v[j].w *= inv;
        p[t + j * 256] = v[j];
        *(uint2*)(hrow + (size_t)(t + j * 256) * 4) = cast4h(v[j]);
    }
}

// ---------------------------------------------------------------------------
extern "C" void kernel_launch(void* const* d_in, const int* in_sizes, int n_in,
                              void* d_out, int out_size)
{
    const float* outp = (const float*)d_in[0];   // [B,Q,H]
    const float* ctx  = (const float*)d_in[1];   // [B,K,H]
    const int*   mask = (const int*)d_in[2];     // [B,Q,K]
    const float* W    = (const float*)d_in[3];   // [H,2H]
    const float* bias = (const float*)d_in[4];   // [H]

    float* out_part  = (float*)d_out;
    float* attn_part = (float*)d_out + OUT_ELEMS;

    __half *oh, *ol, *ch, *cl, *cth, *ath, *mh, *wh;
    cudaGetSymbolAddress((void**)&oh,  g_outp_hi);
    cudaGetSymbolAddress((void**)&ol,  g_outp_lo);
    cudaGetSymbolAddress((void**)&ch,  g_ctx_hi);
    cudaGetSymbolAddress((void**)&cl,  g_ctx_lo);
    cudaGetSymbolAddress((void**)&cth, g_ctxT_hi);
    cudaGetSymbolAddress((void**)&ath, g_attn_hi);
    cudaGetSymbolAddress((void**)&mh,  g_mix_hi);
    cudaGetSymbolAddress((void**)&wh,  g_W_hi);

    cudaFuncSetAttribute(gemm_kernel<0>, cudaFuncAttributeMaxDynamicSharedMemorySize, SMEM_MAX);
    cudaFuncSetAttribute(gemm_kernel<1>, cudaFuncAttributeMaxDynamicSharedMemorySize, SMEM_MAX);
    cudaFuncSetAttribute(gemm_kernel<2>, cudaFuncAttributeMaxDynamicSharedMemorySize, SMEM_MAX);

    // Prep
    {
        size_t n4;
        n4 = (size_t)BBATCH * QQ * HH / 4;
        split_kernel<<<(unsigned)((n4 + 255) / 256), 256>>>(outp, oh, ol, n4);
        n4 = (size_t)HH * 2 * HH / 4;
        cast_kernel<<<(unsigned)((n4 + 255) / 256), 256>>>(W, wh, n4);
        dim3 grid(KK / 32, HH / 32, BBATCH);
        ctx_prep_kernel<<<grid, 256>>>(ctx, ch, cl, cth);
    }
    // scores (+mask) -> attn region (3-term split, fp32 logits)
    {
        dim3 grid(KK / 128, QQ / 128, BBATCH);
        gemm_kernel<0><<<grid, 128, 2 * 4 * ARR_B>>>(oh, ol, nullptr, ch, cl,
                                                     mask, bias, attn_part, mh, out_part);
    }
    // softmax (emits fp32 attn + fp16 hi)
    softmax_kernel<<<BBATCH * QQ, 256>>>(attn_part, ath);
    // mix = attn @ ctx (single-term fp16)
    {
        dim3 grid(HH / 128, QQ / 128, BBATCH);
        gemm_kernel<1><<<grid, 128, 2 * 2 * ARR_B>>>(ath, nullptr, nullptr, cth, nullptr,
                                                     mask, bias, attn_part, mh, out_part);
    }
    // out = tanh([mix|output] @ W^T + b) (single-term fp16)
    {
        dim3 grid(HH / 128, QQ / 128, BBATCH);
        gemm_kernel<2><<<grid, 128, 2 * 2 * ARR_B>>>(mh, nullptr, oh, wh, nullptr,
                                                     mask, bias, attn_part, mh, out_part);
    }
}